// round 12
// baseline (speedup 1.0000x reference)
#include <cuda_runtime.h>
#include <cuda_bf16.h>
#include <cstddef>

// Problem constants (fixed by the reference)
#define NPTS 16384
#define CH   192
#define NH   16
#define NK   43
#define DEPTH 2
#define BN_EPS 1e-5f
#define PTS_PER_BLK 32
#define NPAIRS 16        // pairs per conv block (2 points each)

typedef unsigned long long ull;

// ---------------- scratch (device globals; no allocation allowed) ----------
__device__ float g_tmp1[NPTS * CH];
__device__ float g_tmp2[NPTS * CH];
__device__ float g_tmp3[NPTS * CH];
__device__ float g_featbuf[NPTS * CH];
__device__ float g_stats[6 * 2 * CH];   // 6 stages x (sum[CH], sumsq[CH])
__device__ float g_st[6 * 2 * CH];      // 6 stages x (scale[CH], shift[CH])

// ---------------- f32x2 packed helpers -------------------------------------
__device__ __forceinline__ ull pack2(float x, float y) {
    ull r;
    asm("mov.b64 %0, {%1, %2};" : "=l"(r) : "f"(x), "f"(y));
    return r;
}
__device__ __forceinline__ void ffma2(ull& d, ull a, ull b) {
    asm("fma.rn.f32x2 %0, %1, %2, %0;" : "+l"(d) : "l"(a), "l"(b));
}
__device__ __forceinline__ float2 unpack2(ull v) {
    float2 r;
    asm("mov.b64 {%0, %1}, %2;" : "=f"(r.x), "=f"(r.y) : "l"(v));
    return r;
}
__device__ __forceinline__ float fast_sqrt(float x) {
    float r;
    asm("sqrt.approx.f32 %0, %1;" : "=f"(r) : "f"(x));
    return r;
}

// ---------------------------------------------------------------------------
__global__ void zero_stats_kernel(float* stats) {
    for (int i = threadIdx.x; i < 6 * 2 * CH; i += blockDim.x) stats[i] = 0.f;
}

// finalize BN: scale = g * rsqrt(var+eps), shift = b - mean*scale
__global__ void fin_kernel(const float* __restrict__ stats,
                           const float* __restrict__ g,
                           const float* __restrict__ b,
                           float* __restrict__ st) {
    int c = threadIdx.x;   // 192 threads
    float m = stats[c] * (1.0f / NPTS);
    float v = stats[CH + c] * (1.0f / NPTS) - m * m;
    float s = g[c] * rsqrtf(v + BN_EPS);
    st[c]      = s;
    st[CH + c] = b[c] - m * s;
}

// ---------------------------------------------------------------------------
// GEMM: out[N,192] = act(A)[N,192] @ W[192,192].
// f32x2 packed inner loop with REGISTER-side (a,a) packing — both smem tiles
// remain scalar and identical to the proven layout. Per k: 3 LDS.64 B-pairs
// + 8 packs + 24 FFMA2 (vs 24 LDS.32 + 48 FFMA scalar).
// Optional fused BN+ReLU on A load; accumulates per-channel sum/sumsq.
// Block: 256 threads, 64 rows x 192 cols; thread (tx,ty) owns rows ty*8..+7,
// channel pairs (2tx+64q, 2tx+64q+1), q<3.
__global__ __launch_bounds__(256) void gemm192_kernel(
    const float* __restrict__ A, const float* __restrict__ W,
    float* __restrict__ out, const float* __restrict__ st_in, int fuse,
    float* __restrict__ gsum, float* __restrict__ gsq)
{
    __shared__ __align__(16) float sA[64][32];
    __shared__ __align__(16) float sB[32][192];

    const int tid = threadIdx.x;
    const int tx  = tid & 31;        // 0..31
    const int ty  = tid >> 5;        // 0..7
    const int row0 = blockIdx.x * 64;

    ull acc[8][3];
#pragma unroll
    for (int r = 0; r < 8; r++)
#pragma unroll
        for (int q = 0; q < 3; q++) acc[r][q] = 0ull;

    for (int k0 = 0; k0 < 192; k0 += 32) {
        // --- load A tile (64x32) as float4, optional BN+ReLU transform ---
#pragma unroll
        for (int it = tid; it < 512; it += 256) {
            int r  = it >> 3;
            int kq = it & 7;
            float4 v = *(const float4*)(A + (size_t)(row0 + r) * CH + k0 + kq * 4);
            if (fuse) {
                float4 s = *(const float4*)(st_in + k0 + kq * 4);
                float4 t = *(const float4*)(st_in + CH + k0 + kq * 4);
                v.x = fmaxf(fmaf(v.x, s.x, t.x), 0.f);
                v.y = fmaxf(fmaf(v.y, s.y, t.y), 0.f);
                v.z = fmaxf(fmaf(v.z, s.z, t.z), 0.f);
                v.w = fmaxf(fmaf(v.w, s.w, t.w), 0.f);
            }
            *(float4*)&sA[r][kq * 4] = v;
        }
        // --- load B tile (32x192) ---
#pragma unroll
        for (int it = tid; it < 1536; it += 256) {
            int kk = it / 48;
            int cq = it - kk * 48;
            *(float4*)&sB[kk][cq * 4] =
                *(const float4*)(W + (size_t)(k0 + kk) * CH + cq * 4);
        }
        __syncthreads();

#pragma unroll
        for (int kk4 = 0; kk4 < 8; kk4++) {
            float4 av[8];
#pragma unroll
            for (int r = 0; r < 8; r++)
                av[r] = *(const float4*)&sA[ty * 8 + r][kk4 * 4];
#pragma unroll
            for (int j = 0; j < 4; j++) {
                ull bp[3];
#pragma unroll
                for (int q = 0; q < 3; q++)
                    bp[q] = *(const ull*)&sB[kk4 * 4 + j][2 * tx + 64 * q];
#pragma unroll
                for (int r = 0; r < 8; r++) {
                    float a = (j == 0) ? av[r].x : (j == 1) ? av[r].y
                            : (j == 2) ? av[r].z : av[r].w;
                    ull a2 = pack2(a, a);
                    ffma2(acc[r][0], a2, bp[0]);
                    ffma2(acc[r][1], a2, bp[1]);
                    ffma2(acc[r][2], a2, bp[2]);
                }
            }
        }
        __syncthreads();
    }

    // --- write out + per-channel stats ---
    float cs[3][2], c2[3][2];
#pragma unroll
    for (int q = 0; q < 3; q++) {
        cs[q][0] = cs[q][1] = 0.f;
        c2[q][0] = c2[q][1] = 0.f;
    }
#pragma unroll
    for (int r = 0; r < 8; r++) {
        float* orow = out + (size_t)(row0 + ty * 8 + r) * CH;
#pragma unroll
        for (int q = 0; q < 3; q++) {
            float2 v = unpack2(acc[r][q]);
            *(float2*)(orow + 2 * tx + 64 * q) = v;
            cs[q][0] += v.x;           cs[q][1] += v.y;
            c2[q][0] = fmaf(v.x, v.x, c2[q][0]);
            c2[q][1] = fmaf(v.y, v.y, c2[q][1]);
        }
    }
#pragma unroll
    for (int q = 0; q < 3; q++) {
        atomicAdd(&gsum[2 * tx + 64 * q],     cs[q][0]);
        atomicAdd(&gsum[2 * tx + 64 * q + 1], cs[q][1]);
        atomicAdd(&gsq [2 * tx + 64 * q],     c2[q][0]);
        atomicAdd(&gsq [2 * tx + 64 * q + 1], c2[q][1]);
    }
}

// ---------------------------------------------------------------------------
// Depthwise kernel-point conv, 2-D register-blocked (R8 — best measured).
// One block = 192 threads, 32 points (16 pairs). Thread (cg,hg) =
// (tid>>2, tid&3) owns 4 channels (cg*4..+3) x 4 neighbors (hg*4..+3),
// with the 2 points of the pair packed in f32x2 lanes.
// Per-k loads: 1 LDS.128 (w, 4 ch) + 2 LDS.128 (infl, 8 floats) for
// 16 FFMA2. h-sum completed by a 2-step shfl_xor over the 4-lane quad.
// BN1+ReLU fused at gather; BN2 stats accumulated (hg==0 lanes only).
__global__ __launch_bounds__(192, 4) void conv_kernel(
    const float* __restrict__ coord, const int* __restrict__ ref_idx,
    const float* __restrict__ kp, const float* __restrict__ tmp1,
    const float* __restrict__ st1, const float* __restrict__ Wk,
    float* __restrict__ out,
    float* __restrict__ gsum, float* __restrict__ gsq)
{
    __shared__ __align__(16) float s_wk[NK * CH];        // 33024 B
    __shared__ __align__(16) float s_infl[NK][32];       // 5504 B, [k][2h+p]
    __shared__ int   s_ref[2][NH];
    __shared__ float s_nb[2][NH][3];
    __shared__ float s_kp[NK * 3];

    const int tid  = threadIdx.x;
    const int cg   = tid >> 2;       // channel group 0..47
    const int hg   = tid & 3;        // h group 0..3
    const int base = blockIdx.x * PTS_PER_BLK;

    for (int i = tid; i < NK * CH; i += 192) s_wk[i] = Wk[i];
    for (int i = tid; i < NK * 3;  i += 192) s_kp[i] = kp[i];

    // BN1 consts for my 4 channels
    const float4 s4 = *(const float4*)(st1 + cg * 4);
    const float4 t4 = *(const float4*)(st1 + CH + cg * 4);

    float ls[4] = {0.f, 0.f, 0.f, 0.f};
    float lq[4] = {0.f, 0.f, 0.f, 0.f};

#pragma unroll 1
    for (int pr = 0; pr < NPAIRS; pr++) {
        const int n0 = base + 2 * pr;
        __syncthreads();   // previous iteration done reading s_infl / s_ref
        // --- neighbor indices + relative coords for the 2 points ---
        if (tid < 32) {
            int p = tid >> 4;
            int h = tid & 15;
            int n = n0 + p;
            int r = ref_idx[n * NH + h];
            s_ref[p][h] = r;
            s_nb[p][h][0] = coord[r * 3 + 0] - coord[n * 3 + 0];
            s_nb[p][h][1] = coord[r * 3 + 1] - coord[n * 3 + 1];
            s_nb[p][h][2] = coord[r * 3 + 2] - coord[n * 3 + 2];
        }
        __syncthreads();
        // --- influence [k][2h+p] ---
        for (int i = tid; i < NK * 32; i += 192) {
            int k   = i >> 5;
            int rem = i & 31;
            int h   = rem >> 1;
            int p   = rem & 1;
            float dx = s_nb[p][h][0] - s_kp[k * 3 + 0];
            float dy = s_nb[p][h][1] - s_kp[k * 3 + 1];
            float dz = s_nb[p][h][2] - s_kp[k * 3 + 2];
            float d  = fast_sqrt(fmaf(dx, dx, fmaf(dy, dy, dz * dz)));
            s_infl[k][rem] = fmaxf(1.0f - d, 0.0f);   // SIGMA == 1
        }
        __syncthreads();

        // --- k-loop: acc[j_h][j_c] (f32x2 over points) ---
        ull acc[4][4];
#pragma unroll
        for (int j = 0; j < 4; j++)
#pragma unroll
            for (int c = 0; c < 4; c++) acc[j][c] = 0ull;

#pragma unroll 43
        for (int k = 0; k < NK; k++) {
            const float4 wv = *(const float4*)&s_wk[k * CH + cg * 4];
            ull w0 = pack2(wv.x, wv.x);
            ull w1 = pack2(wv.y, wv.y);
            ull w2 = pack2(wv.z, wv.z);
            ull w3 = pack2(wv.w, wv.w);
            const ulonglong2 ua = *(const ulonglong2*)&s_infl[k][hg * 8];
            const ulonglong2 ub = *(const ulonglong2*)&s_infl[k][hg * 8 + 4];
            ffma2(acc[0][0], ua.x, w0); ffma2(acc[0][1], ua.x, w1);
            ffma2(acc[0][2], ua.x, w2); ffma2(acc[0][3], ua.x, w3);
            ffma2(acc[1][0], ua.y, w0); ffma2(acc[1][1], ua.y, w1);
            ffma2(acc[1][2], ua.y, w2); ffma2(acc[1][3], ua.y, w3);
            ffma2(acc[2][0], ub.x, w0); ffma2(acc[2][1], ub.x, w1);
            ffma2(acc[2][2], ub.x, w2); ffma2(acc[2][3], ub.x, w3);
            ffma2(acc[3][0], ub.y, w0); ffma2(acc[3][1], ub.y, w1);
            ffma2(acc[3][2], ub.y, w2); ffma2(acc[3][3], ub.y, w3);
        }

        // --- gather fc1 rows (BN1+ReLU fused, LDG.128) + partial h-sum ---
        float po0[4] = {0.f, 0.f, 0.f, 0.f};   // point 0
        float po1[4] = {0.f, 0.f, 0.f, 0.f};   // point 1
#pragma unroll
        for (int j = 0; j < 4; j++) {
            int h = hg * 4 + j;
            float4 x0 = *(const float4*)(tmp1 + (size_t)s_ref[0][h] * CH + cg * 4);
            float4 x1 = *(const float4*)(tmp1 + (size_t)s_ref[1][h] * CH + cg * 4);
            x0.x = fmaxf(fmaf(x0.x, s4.x, t4.x), 0.f);
            x0.y = fmaxf(fmaf(x0.y, s4.y, t4.y), 0.f);
            x0.z = fmaxf(fmaf(x0.z, s4.z, t4.z), 0.f);
            x0.w = fmaxf(fmaf(x0.w, s4.w, t4.w), 0.f);
            x1.x = fmaxf(fmaf(x1.x, s4.x, t4.x), 0.f);
            x1.y = fmaxf(fmaf(x1.y, s4.y, t4.y), 0.f);
            x1.z = fmaxf(fmaf(x1.z, s4.z, t4.z), 0.f);
            x1.w = fmaxf(fmaf(x1.w, s4.w, t4.w), 0.f);
            float2 a0 = unpack2(acc[j][0]);
            float2 a1 = unpack2(acc[j][1]);
            float2 a2 = unpack2(acc[j][2]);
            float2 a3 = unpack2(acc[j][3]);
            po0[0] = fmaf(a0.x, x0.x, po0[0]); po1[0] = fmaf(a0.y, x1.x, po1[0]);
            po0[1] = fmaf(a1.x, x0.y, po0[1]); po1[1] = fmaf(a1.y, x1.y, po1[1]);
            po0[2] = fmaf(a2.x, x0.z, po0[2]); po1[2] = fmaf(a2.y, x1.z, po1[2]);
            po0[3] = fmaf(a3.x, x0.w, po0[3]); po1[3] = fmaf(a3.y, x1.w, po1[3]);
        }

        // --- quad reduction over hg (lanes tid&3) ---
#pragma unroll
        for (int c = 0; c < 4; c++) {
            po0[c] += __shfl_xor_sync(0xffffffffu, po0[c], 1);
            po0[c] += __shfl_xor_sync(0xffffffffu, po0[c], 2);
            po1[c] += __shfl_xor_sync(0xffffffffu, po1[c], 1);
            po1[c] += __shfl_xor_sync(0xffffffffu, po1[c], 2);
        }

        if (hg == 0) {
            float4 o0 = make_float4(po0[0], po0[1], po0[2], po0[3]);
            float4 o1 = make_float4(po1[0], po1[1], po1[2], po1[3]);
            *(float4*)(out + (size_t)n0 * CH + cg * 4)       = o0;
            *(float4*)(out + (size_t)(n0 + 1) * CH + cg * 4) = o1;
#pragma unroll
            for (int c = 0; c < 4; c++) {
                ls[c] += po0[c] + po1[c];
                lq[c] = fmaf(po0[c], po0[c], fmaf(po1[c], po1[c], lq[c]));
            }
        }
    }
    if (hg == 0) {
#pragma unroll
        for (int c = 0; c < 4; c++) {
            atomicAdd(&gsum[cg * 4 + c], ls[c]);
            atomicAdd(&gsq [cg * 4 + c], lq[c]);
        }
    }
}

// ---------------------------------------------------------------------------
// feat_out = relu(identity + BN3(tmp3))   (vectorized float4)
__global__ __launch_bounds__(256) void apply3_kernel(
    const float4* __restrict__ idf, const float4* __restrict__ t3,
    const float* __restrict__ st, float4* __restrict__ outf)
{
    int i  = blockIdx.x * blockDim.x + threadIdx.x;   // < NPTS*CH/4
    int cq = i % (CH / 4);
    float4 s = *(const float4*)(st + cq * 4);
    float4 t = *(const float4*)(st + CH + cq * 4);
    float4 x = t3[i];
    float4 d = idf[i];
    float4 r;
    r.x = fmaxf(d.x + fmaf(x.x, s.x, t.x), 0.f);
    r.y = fmaxf(d.y + fmaf(x.y, s.y, t.y), 0.f);
    r.z = fmaxf(d.z + fmaf(x.z, s.z, t.z), 0.f);
    r.w = fmaxf(d.w + fmaf(x.w, s.w, t.w), 0.f);
    outf[i] = r;
}

// ---------------------------------------------------------------------------
extern "C" void kernel_launch(void* const* d_in, const int* in_sizes, int n_in,
                              void* d_out, int out_size)
{
    const float* coord   = (const float*)d_in[0];
    const float* feat    = (const float*)d_in[1];
    const int*   ref_idx = (const int*)  d_in[2];
    const float* kp      = (const float*)d_in[3];
    const float* W1      = (const float*)d_in[4];
    const float* Wk      = (const float*)d_in[5];
    const float* W3      = (const float*)d_in[6];
    const float* g1      = (const float*)d_in[7];
    const float* b1      = (const float*)d_in[8];
    const float* g2      = (const float*)d_in[9];
    const float* b2      = (const float*)d_in[10];
    const float* g3      = (const float*)d_in[11];
    const float* b3      = (const float*)d_in[12];
    float* out = (float*)d_out;

    float *tmp1, *tmp2, *tmp3, *featbuf, *stats, *st;
    cudaGetSymbolAddress((void**)&tmp1,    g_tmp1);
    cudaGetSymbolAddress((void**)&tmp2,    g_tmp2);
    cudaGetSymbolAddress((void**)&tmp3,    g_tmp3);
    cudaGetSymbolAddress((void**)&featbuf, g_featbuf);
    cudaGetSymbolAddress((void**)&stats,   g_stats);
    cudaGetSymbolAddress((void**)&st,      g_st);

    zero_stats_kernel<<<1, 256>>>(stats);

    const int NVEC = NPTS * CH / 4;             // 786432
    for (int i = 0; i < DEPTH; i++) {
        const float* fin_ = (i == 0) ? feat : featbuf;
        float* fout = (i == DEPTH - 1) ? out : featbuf;
        const int s0 = 3 * i + 0, s1 = 3 * i + 1, s2 = 3 * i + 2;

        // fc1 (+BN1 stats)
        gemm192_kernel<<<NPTS / 64, 256>>>(
            fin_, W1 + (size_t)i * CH * CH, tmp1, nullptr, 0,
            stats + s0 * 2 * CH, stats + s0 * 2 * CH + CH);
        fin_kernel<<<1, CH>>>(stats + s0 * 2 * CH, g1 + i * CH, b1 + i * CH,
                              st + s0 * 2 * CH);

        // KP depthwise conv (BN1+ReLU fused at gather; BN2 stats out)
        conv_kernel<<<NPTS / PTS_PER_BLK, CH>>>(
            coord, ref_idx, kp, tmp1, st + s0 * 2 * CH,
            Wk + (size_t)i * NK * CH, tmp2,
            stats + s1 * 2 * CH, stats + s1 * 2 * CH + CH);
        fin_kernel<<<1, CH>>>(stats + s1 * 2 * CH, g2 + i * CH, b2 + i * CH,
                              st + s1 * 2 * CH);

        // fc3 (BN2+ReLU fused on A load; BN3 stats out)
        gemm192_kernel<<<NPTS / 64, 256>>>(
            tmp2, W3 + (size_t)i * CH * CH, tmp3, st + s1 * 2 * CH, 1,
            stats + s2 * 2 * CH, stats + s2 * 2 * CH + CH);
        fin_kernel<<<1, CH>>>(stats + s2 * 2 * CH, g3 + i * CH, b3 + i * CH,
                              st + s2 * 2 * CH);

        // skip + BN3 + ReLU
        apply3_kernel<<<NVEC / 256, 256>>>(
            (const float4*)fin_, (const float4*)tmp3, st + s2 * 2 * CH,
            (float4*)fout);
    }
}

// round 13
// speedup vs baseline: 1.2130x; 1.2130x over previous
#include <cuda_runtime.h>
#include <cuda_bf16.h>
#include <cstddef>

// Problem constants (fixed by the reference)
#define NPTS 16384
#define CH   192
#define NH   16
#define NK   43
#define DEPTH 2
#define BN_EPS 1e-5f
#define PTS_PER_BLK 32
#define NPAIRS 16        // pairs per conv block (2 points each)

typedef unsigned long long ull;

// ---------------- scratch (device globals; no allocation allowed) ----------
__device__ float g_tmp1[NPTS * CH];
__device__ float g_tmp2[NPTS * CH];
__device__ float g_tmp3[NPTS * CH];
__device__ float g_featbuf[NPTS * CH];
__device__ float g_stats[6 * 2 * CH];   // 6 stages x (sum[CH], sumsq[CH])

// ---------------- f32x2 packed helpers (conv only) --------------------------
__device__ __forceinline__ ull pack2(float x, float y) {
    ull r;
    asm("mov.b64 %0, {%1, %2};" : "=l"(r) : "f"(x), "f"(y));
    return r;
}
__device__ __forceinline__ void ffma2(ull& d, ull a, ull b) {
    asm("fma.rn.f32x2 %0, %1, %2, %0;" : "+l"(d) : "l"(a), "l"(b));
}
__device__ __forceinline__ float2 unpack2(ull v) {
    float2 r;
    asm("mov.b64 {%0, %1}, %2;" : "=f"(r.x), "=f"(r.y) : "l"(v));
    return r;
}
__device__ __forceinline__ float fast_sqrt(float x) {
    float r;
    asm("sqrt.approx.f32 %0, %1;" : "=f"(r) : "f"(x));
    return r;
}

// Per-block BN finalize: 192 scale/shift values into smem from global stats.
// stats complete because the producing kernel finished (kernel boundary).
__device__ __forceinline__ void bn_finalize_smem(
    float* s_st, const float* __restrict__ stats,
    const float* __restrict__ g, const float* __restrict__ b, int tid)
{
    if (tid < CH) {
        float m = stats[tid] * (1.0f / NPTS);
        float v = stats[CH + tid] * (1.0f / NPTS) - m * m;
        float s = g[tid] * rsqrtf(v + BN_EPS);
        s_st[tid]      = s;
        s_st[CH + tid] = b[tid] - m * s;
    }
}

// ---------------------------------------------------------------------------
__global__ void zero_stats_kernel(float* stats) {
    for (int i = threadIdx.x; i < 6 * 2 * CH; i += blockDim.x) stats[i] = 0.f;
}

// ---------------------------------------------------------------------------
// GEMM: out[N,192] = act(A)[N,192] @ W[192,192]  (scalar — proven ~16 TFMA/s).
// fuse != 0: BN+ReLU on A load, with scale/shift finalized per-block in smem
// from (stats_in, g_in, b_in). Accumulates per-channel sum/sumsq for next BN.
// Block: 256 threads, 64 rows x 192 cols tile.
__global__ __launch_bounds__(256) void gemm192_kernel(
    const float* __restrict__ A, const float* __restrict__ W,
    float* __restrict__ out,
    const float* __restrict__ stats_in, const float* __restrict__ g_in,
    const float* __restrict__ b_in, int fuse,
    float* __restrict__ gsum, float* __restrict__ gsq)
{
    __shared__ __align__(16) float sA[64][32];
    __shared__ __align__(16) float sB[32][192];
    __shared__ __align__(16) float s_st[2 * CH];

    const int tid = threadIdx.x;
    const int tx  = tid & 31;        // 0..31
    const int ty  = tid >> 5;        // 0..7
    const int row0 = blockIdx.x * 64;

    if (fuse) bn_finalize_smem(s_st, stats_in, g_in, b_in, tid);

    float acc[8][6];
#pragma unroll
    for (int r = 0; r < 8; r++)
#pragma unroll
        for (int q = 0; q < 6; q++) acc[r][q] = 0.f;

    if (fuse) __syncthreads();       // s_st ready before first A-tile load

    for (int k0 = 0; k0 < 192; k0 += 32) {
        // --- load A tile (64x32) as float4, optional BN+ReLU transform ---
#pragma unroll
        for (int it = tid; it < 512; it += 256) {
            int r  = it >> 3;
            int kq = it & 7;
            float4 v = *(const float4*)(A + (size_t)(row0 + r) * CH + k0 + kq * 4);
            if (fuse) {
                float4 s = *(const float4*)(s_st + k0 + kq * 4);
                float4 t = *(const float4*)(s_st + CH + k0 + kq * 4);
                v.x = fmaxf(fmaf(v.x, s.x, t.x), 0.f);
                v.y = fmaxf(fmaf(v.y, s.y, t.y), 0.f);
                v.z = fmaxf(fmaf(v.z, s.z, t.z), 0.f);
                v.w = fmaxf(fmaf(v.w, s.w, t.w), 0.f);
            }
            *(float4*)&sA[r][kq * 4] = v;
        }
        // --- load B tile (32x192) ---
#pragma unroll
        for (int it = tid; it < 1536; it += 256) {
            int kk = it / 48;
            int cq = it - kk * 48;
            *(float4*)&sB[kk][cq * 4] =
                *(const float4*)(W + (size_t)(k0 + kk) * CH + cq * 4);
        }
        __syncthreads();

#pragma unroll
        for (int kk4 = 0; kk4 < 8; kk4++) {
            float4 av[8];
#pragma unroll
            for (int r = 0; r < 8; r++)
                av[r] = *(const float4*)&sA[ty * 8 + r][kk4 * 4];
#pragma unroll
            for (int j = 0; j < 4; j++) {
                float bv[6];
#pragma unroll
                for (int q = 0; q < 6; q++)
                    bv[q] = sB[kk4 * 4 + j][tx + 32 * q];
#pragma unroll
                for (int r = 0; r < 8; r++) {
                    float a = (j == 0) ? av[r].x : (j == 1) ? av[r].y
                            : (j == 2) ? av[r].z : av[r].w;
#pragma unroll
                    for (int q = 0; q < 6; q++)
                        acc[r][q] = fmaf(a, bv[q], acc[r][q]);
                }
            }
        }
        __syncthreads();
    }

    // --- write out + per-channel stats ---
    float cs[6], c2[6];
#pragma unroll
    for (int q = 0; q < 6; q++) { cs[q] = 0.f; c2[q] = 0.f; }
#pragma unroll
    for (int r = 0; r < 8; r++) {
        float* orow = out + (size_t)(row0 + ty * 8 + r) * CH;
#pragma unroll
        for (int q = 0; q < 6; q++) {
            float v = acc[r][q];
            orow[tx + 32 * q] = v;
            cs[q] += v;
            c2[q] = fmaf(v, v, c2[q]);
        }
    }
#pragma unroll
    for (int q = 0; q < 6; q++) {
        atomicAdd(&gsum[tx + 32 * q], cs[q]);
        atomicAdd(&gsq [tx + 32 * q], c2[q]);
    }
}

// ---------------------------------------------------------------------------
// Depthwise kernel-point conv, 2-D register-blocked (R8 — best measured),
// with BN1-finalize folded in (per-block from stats0 + g1/b1).
// One block = 192 threads, 32 points (16 pairs). Thread (cg,hg) =
// (tid>>2, tid&3) owns 4 channels x 4 neighbors, 2 points packed f32x2.
// Per-k: 1 LDS.128 (w) + 2 LDS.128 (infl) for 16 FFMA2.
// h-sum via 2-step shfl_xor over the 4-lane quad.
__global__ __launch_bounds__(192, 4) void conv_kernel(
    const float* __restrict__ coord, const int* __restrict__ ref_idx,
    const float* __restrict__ kp, const float* __restrict__ tmp1,
    const float* __restrict__ stats0, const float* __restrict__ g1,
    const float* __restrict__ b1, const float* __restrict__ Wk,
    float* __restrict__ out,
    float* __restrict__ gsum, float* __restrict__ gsq)
{
    __shared__ __align__(16) float s_wk[NK * CH];        // 33024 B
    __shared__ __align__(16) float s_infl[NK][32];       // 5504 B, [k][2h+p]
    __shared__ __align__(16) float s_st[2 * CH];
    __shared__ int   s_ref[2][NH];
    __shared__ float s_nb[2][NH][3];
    __shared__ float s_kp[NK * 3];

    const int tid  = threadIdx.x;
    const int cg   = tid >> 2;       // channel group 0..47
    const int hg   = tid & 3;        // h group 0..3
    const int base = blockIdx.x * PTS_PER_BLK;

    bn_finalize_smem(s_st, stats0, g1, b1, tid);
    for (int i = tid; i < NK * CH; i += 192) s_wk[i] = Wk[i];
    for (int i = tid; i < NK * 3;  i += 192) s_kp[i] = kp[i];
    __syncthreads();                 // s_st ready

    // BN1 consts for my 4 channels
    const float4 s4 = *(const float4*)(s_st + cg * 4);
    const float4 t4 = *(const float4*)(s_st + CH + cg * 4);

    float ls[4] = {0.f, 0.f, 0.f, 0.f};
    float lq[4] = {0.f, 0.f, 0.f, 0.f};

#pragma unroll 1
    for (int pr = 0; pr < NPAIRS; pr++) {
        const int n0 = base + 2 * pr;
        __syncthreads();   // previous iteration done reading s_infl / s_ref
        // --- neighbor indices + relative coords for the 2 points ---
        if (tid < 32) {
            int p = tid >> 4;
            int h = tid & 15;
            int n = n0 + p;
            int r = ref_idx[n * NH + h];
            s_ref[p][h] = r;
            s_nb[p][h][0] = coord[r * 3 + 0] - coord[n * 3 + 0];
            s_nb[p][h][1] = coord[r * 3 + 1] - coord[n * 3 + 1];
            s_nb[p][h][2] = coord[r * 3 + 2] - coord[n * 3 + 2];
        }
        __syncthreads();
        // --- influence [k][2h+p] ---
        for (int i = tid; i < NK * 32; i += 192) {
            int k   = i >> 5;
            int rem = i & 31;
            int h   = rem >> 1;
            int p   = rem & 1;
            float dx = s_nb[p][h][0] - s_kp[k * 3 + 0];
            float dy = s_nb[p][h][1] - s_kp[k * 3 + 1];
            float dz = s_nb[p][h][2] - s_kp[k * 3 + 2];
            float d  = fast_sqrt(fmaf(dx, dx, fmaf(dy, dy, dz * dz)));
            s_infl[k][rem] = fmaxf(1.0f - d, 0.0f);   // SIGMA == 1
        }
        __syncthreads();

        // --- k-loop: acc[j_h][j_c] (f32x2 over points) ---
        ull acc[4][4];
#pragma unroll
        for (int j = 0; j < 4; j++)
#pragma unroll
            for (int c = 0; c < 4; c++) acc[j][c] = 0ull;

#pragma unroll 43
        for (int k = 0; k < NK; k++) {
            const float4 wv = *(const float4*)&s_wk[k * CH + cg * 4];
            ull w0 = pack2(wv.x, wv.x);
            ull w1 = pack2(wv.y, wv.y);
            ull w2 = pack2(wv.z, wv.z);
            ull w3 = pack2(wv.w, wv.w);
            const ulonglong2 ua = *(const ulonglong2*)&s_infl[k][hg * 8];
            const ulonglong2 ub = *(const ulonglong2*)&s_infl[k][hg * 8 + 4];
            ffma2(acc[0][0], ua.x, w0); ffma2(acc[0][1], ua.x, w1);
            ffma2(acc[0][2], ua.x, w2); ffma2(acc[0][3], ua.x, w3);
            ffma2(acc[1][0], ua.y, w0); ffma2(acc[1][1], ua.y, w1);
            ffma2(acc[1][2], ua.y, w2); ffma2(acc[1][3], ua.y, w3);
            ffma2(acc[2][0], ub.x, w0); ffma2(acc[2][1], ub.x, w1);
            ffma2(acc[2][2], ub.x, w2); ffma2(acc[2][3], ub.x, w3);
            ffma2(acc[3][0], ub.y, w0); ffma2(acc[3][1], ub.y, w1);
            ffma2(acc[3][2], ub.y, w2); ffma2(acc[3][3], ub.y, w3);
        }

        // --- gather fc1 rows (BN1+ReLU fused, LDG.128) + partial h-sum ---
        float po0[4] = {0.f, 0.f, 0.f, 0.f};   // point 0
        float po1[4] = {0.f, 0.f, 0.f, 0.f};   // point 1
#pragma unroll
        for (int j = 0; j < 4; j++) {
            int h = hg * 4 + j;
            float4 x0 = *(const float4*)(tmp1 + (size_t)s_ref[0][h] * CH + cg * 4);
            float4 x1 = *(const float4*)(tmp1 + (size_t)s_ref[1][h] * CH + cg * 4);
            x0.x = fmaxf(fmaf(x0.x, s4.x, t4.x), 0.f);
            x0.y = fmaxf(fmaf(x0.y, s4.y, t4.y), 0.f);
            x0.z = fmaxf(fmaf(x0.z, s4.z, t4.z), 0.f);
            x0.w = fmaxf(fmaf(x0.w, s4.w, t4.w), 0.f);
            x1.x = fmaxf(fmaf(x1.x, s4.x, t4.x), 0.f);
            x1.y = fmaxf(fmaf(x1.y, s4.y, t4.y), 0.f);
            x1.z = fmaxf(fmaf(x1.z, s4.z, t4.z), 0.f);
            x1.w = fmaxf(fmaf(x1.w, s4.w, t4.w), 0.f);
            float2 a0 = unpack2(acc[j][0]);
            float2 a1 = unpack2(acc[j][1]);
            float2 a2 = unpack2(acc[j][2]);
            float2 a3 = unpack2(acc[j][3]);
            po0[0] = fmaf(a0.x, x0.x, po0[0]); po1[0] = fmaf(a0.y, x1.x, po1[0]);
            po0[1] = fmaf(a1.x, x0.y, po0[1]); po1[1] = fmaf(a1.y, x1.y, po1[1]);
            po0[2] = fmaf(a2.x, x0.z, po0[2]); po1[2] = fmaf(a2.y, x1.z, po1[2]);
            po0[3] = fmaf(a3.x, x0.w, po0[3]); po1[3] = fmaf(a3.y, x1.w, po1[3]);
        }

        // --- quad reduction over hg (lanes tid&3) ---
#pragma unroll
        for (int c = 0; c < 4; c++) {
            po0[c] += __shfl_xor_sync(0xffffffffu, po0[c], 1);
            po0[c] += __shfl_xor_sync(0xffffffffu, po0[c], 2);
            po1[c] += __shfl_xor_sync(0xffffffffu, po1[c], 1);
            po1[c] += __shfl_xor_sync(0xffffffffu, po1[c], 2);
        }

        if (hg == 0) {
            float4 o0 = make_float4(po0[0], po0[1], po0[2], po0[3]);
            float4 o1 = make_float4(po1[0], po1[1], po1[2], po1[3]);
            *(float4*)(out + (size_t)n0 * CH + cg * 4)       = o0;
            *(float4*)(out + (size_t)(n0 + 1) * CH + cg * 4) = o1;
#pragma unroll
            for (int c = 0; c < 4; c++) {
                ls[c] += po0[c] + po1[c];
                lq[c] = fmaf(po0[c], po0[c], fmaf(po1[c], po1[c], lq[c]));
            }
        }
    }
    if (hg == 0) {
#pragma unroll
        for (int c = 0; c < 4; c++) {
            atomicAdd(&gsum[cg * 4 + c], ls[c]);
            atomicAdd(&gsq [cg * 4 + c], lq[c]);
        }
    }
}

// ---------------------------------------------------------------------------
// feat_out = relu(identity + BN3(tmp3)), BN3-finalize folded in.
// 256 threads; vectorized float4.
__global__ __launch_bounds__(256) void apply3_kernel(
    const float4* __restrict__ idf, const float4* __restrict__ t3,
    const float* __restrict__ stats, const float* __restrict__ g,
    const float* __restrict__ b, float4* __restrict__ outf)
{
    __shared__ __align__(16) float s_st[2 * CH];
    const int tid = threadIdx.x;
    bn_finalize_smem(s_st, stats, g, b, tid);
    __syncthreads();

    int i  = blockIdx.x * blockDim.x + tid;   // < NPTS*CH/4
    int cq = i % (CH / 4);
    float4 s = *(const float4*)(s_st + cq * 4);
    float4 t = *(const float4*)(s_st + CH + cq * 4);
    float4 x = t3[i];
    float4 d = idf[i];
    float4 r;
    r.x = fmaxf(d.x + fmaf(x.x, s.x, t.x), 0.f);
    r.y = fmaxf(d.y + fmaf(x.y, s.y, t.y), 0.f);
    r.z = fmaxf(d.z + fmaf(x.z, s.z, t.z), 0.f);
    r.w = fmaxf(d.w + fmaf(x.w, s.w, t.w), 0.f);
    outf[i] = r;
}

// ---------------------------------------------------------------------------
extern "C" void kernel_launch(void* const* d_in, const int* in_sizes, int n_in,
                              void* d_out, int out_size)
{
    const float* coord   = (const float*)d_in[0];
    const float* feat    = (const float*)d_in[1];
    const int*   ref_idx = (const int*)  d_in[2];
    const float* kp      = (const float*)d_in[3];
    const float* W1      = (const float*)d_in[4];
    const float* Wk      = (const float*)d_in[5];
    const float* W3      = (const float*)d_in[6];
    const float* g1      = (const float*)d_in[7];
    const float* b1      = (const float*)d_in[8];
    const float* g2      = (const float*)d_in[9];
    const float* b2      = (const float*)d_in[10];
    const float* g3      = (const float*)d_in[11];
    const float* b3      = (const float*)d_in[12];
    float* out = (float*)d_out;

    float *tmp1, *tmp2, *tmp3, *featbuf, *stats;
    cudaGetSymbolAddress((void**)&tmp1,    g_tmp1);
    cudaGetSymbolAddress((void**)&tmp2,    g_tmp2);
    cudaGetSymbolAddress((void**)&tmp3,    g_tmp3);
    cudaGetSymbolAddress((void**)&featbuf, g_featbuf);
    cudaGetSymbolAddress((void**)&stats,   g_stats);

    zero_stats_kernel<<<1, 256>>>(stats);

    const int NVEC = NPTS * CH / 4;             // 786432
    for (int i = 0; i < DEPTH; i++) {
        const float* fin_ = (i == 0) ? feat : featbuf;
        float* fout = (i == DEPTH - 1) ? out : featbuf;
        const int s0 = 3 * i + 0, s1 = 3 * i + 1, s2 = 3 * i + 2;
        float* st0 = stats + s0 * 2 * CH;
        float* st1 = stats + s1 * 2 * CH;
        float* st2 = stats + s2 * 2 * CH;

        // fc1 (+BN1 stats)
        gemm192_kernel<<<NPTS / 64, 256>>>(
            fin_, W1 + (size_t)i * CH * CH, tmp1,
            nullptr, nullptr, nullptr, 0,
            st0, st0 + CH);

        // KP depthwise conv (BN1 finalize folded; BN1+ReLU fused at gather;
        // BN2 stats out)
        conv_kernel<<<NPTS / PTS_PER_BLK, CH>>>(
            coord, ref_idx, kp, tmp1,
            st0, g1 + i * CH, b1 + i * CH,
            Wk + (size_t)i * NK * CH, tmp2,
            st1, st1 + CH);

        // fc3 (BN2 finalize folded; BN2+ReLU fused on A load; BN3 stats out)
        gemm192_kernel<<<NPTS / 64, 256>>>(
            tmp2, W3 + (size_t)i * CH * CH, tmp3,
            st1, g2 + i * CH, b2 + i * CH, 1,
            st2, st2 + CH);

        // skip + BN3 + ReLU (BN3 finalize folded)
        apply3_kernel<<<NVEC / 256, 256>>>(
            (const float4*)fin_, (const float4*)tmp3,
            st2, g3 + i * CH, b3 + i * CH,
            (float4*)fout);
    }
}